// round 10
// baseline (speedup 1.0000x reference)
#include <cuda_runtime.h>

// STN bilinear sampler, v10 — v9 (strip-level clamp dedup) with PLAIN stores.
// Single-variable experiment vs v9: drop __stcs so output writes are normal
// write-back; L2 (126MB) batches/reorders the DRAM drain instead of the eager
// evict-first stream. Everything else identical to v9.

#define B_ 32
#define H_ 256
#define W_ 256
#define ROWS_ 8
#define STEP (2.0f / 255.0f)
#define FULL 0xFFFFFFFFu

struct Ctx {
    float t0, t1, t2, t3, t4, t5;
    float gx;
    int basep, cg, oy, obase;
};

// MODE bit0 = x-duplicated (x0c==x1c), bit1 = y-duplicated (y0c==y1c)
template <int MODE>
__device__ __forceinline__ void run_strip(const Ctx& c,
                                          const float4* __restrict__ xf,
                                          float4* __restrict__ out)
{
#pragma unroll
    for (int k = 0; k < ROWS_; k++) {
        float gy = -1.0f + (float)(c.oy + k) * STEP;

        // identical formula to reference: 0.5*(T·g + 1)*N, truncate toward zero
        float sx = 0.5f * (c.t0 * c.gx + c.t1 * gy + c.t2 + 1.0f) * (float)W_;
        float sy = 0.5f * (c.t3 * c.gx + c.t4 * gy + c.t5 + 1.0f) * (float)H_;

        int x0 = (int)sx;
        int y0 = (int)sy;

        int x0c = min(max(x0, 0), W_ - 1);
        int x1c = min(max(x0 + 1, 0), W_ - 1);
        int y0c = min(max(y0, 0), H_ - 1);
        int y1c = min(max(y0 + 1, 0), H_ - 1);

        float x0f = (float)x0c, x1f = (float)x1c;
        float y0f = (float)y0c, y1f = (float)y1c;

        float wa = (x1f - sx) * (y1f - sy);
        float wb = (x1f - sx) * (sy - y0f);
        float wc = (sx - x0f) * (y1f - sy);
        float wd = (sx - x0f) * (sy - y0f);

        int dx = (x1c - x0c) << 3;
        int ia = ((c.basep + (y0c << 8) + x0c) << 3) + c.cg;
        int ib = ((c.basep + (y1c << 8) + x0c) << 3) + c.cg;

        float4 pa = __ldg(xf + ia);
        float4 pb = (MODE & 2) ? pa : __ldg(xf + ib);
        float4 pc = (MODE & 1) ? pa : __ldg(xf + ia + dx);
        float4 pd = (MODE & 1) ? pb : ((MODE & 2) ? pc : __ldg(xf + ib + dx));

        float4 o;
        o.x = wa * pa.x + wb * pb.x + wc * pc.x + wd * pd.x;
        o.y = wa * pa.y + wb * pb.y + wc * pc.y + wd * pd.y;
        o.z = wa * pa.z + wb * pb.z + wc * pc.z + wd * pd.z;
        o.w = wa * pa.w + wb * pb.w + wc * pc.w + wd * pd.w;

        // plain write-back store: let L2 batch the DRAM drain
        out[c.obase + (k << 11)] = o;   // + k * W_ * 8
    }
}

__global__ __launch_bounds__(256) void stn_kernel(
    const float4* __restrict__ xf,
    const float* __restrict__ theta,
    float4* __restrict__ out)
{
    int gid = blockIdx.x * blockDim.x + threadIdx.x;   // [0, 2^21)
    Ctx c;
    c.cg  = gid & 7;
    int ox  = (gid >> 3) & 255;
    int oy8 = (gid >> 11) & 31;
    int b   = gid >> 16;
    c.oy = oy8 << 3;

    // theta via 3x LDG.64 (8B-aligned: b*24 bytes)
    const float2* t2p = (const float2*)(theta + b * 6);
    float2 q0 = __ldg(t2p + 0);
    float2 q1 = __ldg(t2p + 1);
    float2 q2 = __ldg(t2p + 2);
    c.t0 = q0.x; c.t1 = q0.y; c.t2 = q1.x;
    c.t3 = q1.y; c.t4 = q2.x; c.t5 = q2.y;

    c.gx = -1.0f + (float)ox * STEP;
    c.basep = b << 16;
    c.obase = ((c.basep + (c.oy << 8) + ox) << 3) + c.cg;

    // ---- strip classification via endpoint rows (sx,sy affine in oy) ----
    float gyA = -1.0f + (float)c.oy * STEP;
    float gyB = -1.0f + (float)(c.oy + ROWS_ - 1) * STEP;

    float sxA = 0.5f * (c.t0 * c.gx + c.t1 * gyA + c.t2 + 1.0f) * (float)W_;
    float syA = 0.5f * (c.t3 * c.gx + c.t4 * gyA + c.t5 + 1.0f) * (float)H_;
    float sxB = 0.5f * (c.t0 * c.gx + c.t1 * gyB + c.t2 + 1.0f) * (float)W_;
    float syB = 0.5f * (c.t3 * c.gx + c.t4 * gyB + c.t5 + 1.0f) * (float)H_;

    // conservative margins (fp rounding guard): claim dup only when certain
    bool xlo = (sxA <= -1.01f)  && (sxB <= -1.01f);
    bool xhi = (sxA >= 255.01f) && (sxB >= 255.01f);
    bool ylo = (syA <= -1.01f)  && (syB <= -1.01f);
    bool yhi = (syA >= 255.01f) && (syB >= 255.01f);

    bool ux = __all_sync(FULL, xlo) || __all_sync(FULL, xhi);
    bool uy = __all_sync(FULL, ylo) || __all_sync(FULL, yhi);

    if (ux) {
        if (uy) run_strip<3>(c, xf, out);
        else    run_strip<1>(c, xf, out);
    } else {
        if (uy) run_strip<2>(c, xf, out);
        else    run_strip<0>(c, xf, out);
    }
}

extern "C" void kernel_launch(void* const* d_in, const int* in_sizes, int n_in,
                              void* d_out, int out_size)
{
    const float4* x    = (const float4*)d_in[0];
    const float* theta = (const float*)d_in[1];
    float4* out = (float4*)d_out;

    int total_threads = B_ * (H_ / ROWS_) * W_ * 8;   // 2,097,152
    int block = 256;
    int grid = total_threads / block;                  // 8,192
    stn_kernel<<<grid, block>>>(x, theta, out);
}